// round 15
// baseline (speedup 1.0000x reference)
#include <cuda_runtime.h>
#include <cuda_fp16.h>
#include <math.h>
#include <stdint.h>

#define BB     2
#define SS     4096
#define DD     1024
#define HH     16
#define DH     64
#define SEGLEN 512
#define PP     16
#define NWIN   8
#define INNER  1024
#define NTOK   (BB * SS)   // 8192
#define TOTKEY (SEGLEN + PP)  // 528

// ---------------- scratch (device globals; no allocation allowed) ----------
__device__ __half  g_qh[NTOK * 3 * INNER];      // qkv hi plane
__device__ __half  g_ql[NTOK * 3 * INNER];      // qkv lo plane (V cols unused)
__device__ __half  g_ah[NTOK * DD];             // rmsnorm out (fp16, single plane)
__device__ __half  g_ch[NTOK * INNER];          // attn out (fp16, single plane)
__device__ __half  g_bhq[3 * INNER * DD];       // w_qkv^T fp16  [N,K]
__device__ __half  g_bho[DD * INNER];           // w_out^T fp16  [N,K]
__device__ __half  g_pmkh[HH * PP * DH];        // pm_k hi
__device__ __half  g_pmkl[HH * PP * DH];
__device__ __half  g_pmvh[HH * PP * DH];        // pm_v (fp16 single)

// ---------------- PTX helpers (sm_80-class only; no 'a'-features) ----------
__device__ __forceinline__ uint32_t smem_u32(const void* p) {
    uint32_t a;
    asm("{ .reg .u64 t; cvta.to.shared.u64 t, %1; cvt.u32.u64 %0, t; }" : "=r"(a) : "l"(p));
    return a;
}

#define CP_ASYNC16(saddr, gptr) \
    asm volatile("cp.async.cg.shared.global [%0], [%1], 16;" :: "r"(saddr), "l"(gptr))
#define CP_COMMIT() asm volatile("cp.async.commit_group;" ::: "memory")
#define CP_WAIT(n)  asm volatile("cp.async.wait_group %0;" :: "n"(n) : "memory")

#define LDSM4(r, a)                                                                 \
    asm volatile("ldmatrix.sync.aligned.m8n8.x4.shared.b16 {%0,%1,%2,%3}, [%4];"    \
        : "=r"((r)[0]), "=r"((r)[1]), "=r"((r)[2]), "=r"((r)[3]) : "r"(a))

#define LDSM4T(r, a)                                                                \
    asm volatile("ldmatrix.sync.aligned.m8n8.x4.trans.shared.b16 {%0,%1,%2,%3}, [%4];" \
        : "=r"((r)[0]), "=r"((r)[1]), "=r"((r)[2]), "=r"((r)[3]) : "r"(a))

#define MMA_F16(d, a, b)                                                            \
    asm volatile("mma.sync.aligned.m16n8k16.row.col.f32.f16.f16.f32 "               \
        "{%0,%1,%2,%3}, {%4,%5,%6,%7}, {%8,%9}, {%0,%1,%2,%3};"                     \
        : "+f"((d)[0]), "+f"((d)[1]), "+f"((d)[2]), "+f"((d)[3])                    \
        : "r"((a)[0]), "r"((a)[1]), "r"((a)[2]), "r"((a)[3]), "r"((b)[0]), "r"((b)[1]))

__device__ __forceinline__ uint32_t packh(float x, float y) {
    __half2 t = __floats2half2_rn(x, y);
    return *reinterpret_cast<uint32_t*>(&t);
}
__device__ __forceinline__ void split2(float x, float y, uint32_t& ph, uint32_t& pl) {
    __half hx = __float2half_rn(x), hy = __float2half_rn(y);
    __half2 hp = __halves2half2(hx, hy);
    ph = *reinterpret_cast<uint32_t*>(&hp);
    pl = packh(x - __half2float(hx), y - __half2float(hy));
}

// ---------------------------------------------------------------------------
// Kernel 1: RMSNorm -> single fp16 plane.
// ---------------------------------------------------------------------------
__global__ __launch_bounds__(256) void rmsnorm_split_k(const float* __restrict__ x,
                                                       const float* __restrict__ gamma,
                                                       __half* __restrict__ Ah) {
    int row = blockIdx.x;
    int t = threadIdx.x;
    const float4* xr = reinterpret_cast<const float4*>(x + (size_t)row * DD);
    const float4* gr = reinterpret_cast<const float4*>(gamma);

    float4 v = xr[t];
    float ss = v.x * v.x + v.y * v.y + v.z * v.z + v.w * v.w;
    #pragma unroll
    for (int o = 16; o > 0; o >>= 1) ss += __shfl_xor_sync(0xffffffffu, ss, o);

    __shared__ float red[8];
    int warp = t >> 5, lane = t & 31;
    if (lane == 0) red[warp] = ss;
    __syncthreads();
    if (warp == 0) {
        float s2 = (lane < 8) ? red[lane] : 0.0f;
        #pragma unroll
        for (int o = 16; o > 0; o >>= 1) s2 += __shfl_xor_sync(0xffffffffu, s2, o);
        if (lane == 0) red[0] = s2;
    }
    __syncthreads();

    float inv = rsqrtf(red[0] * (1.0f / DD) + 1e-6f);
    float4 g = gr[t];
    uint2 hi;
    hi.x = packh(v.x * inv * g.x, v.y * inv * g.y);
    hi.y = packh(v.z * inv * g.z, v.w * inv * g.w);
    *reinterpret_cast<uint2*>(Ah + (size_t)row * DD + t * 4) = hi;
}

// ---------------------------------------------------------------------------
// Kernel 2: fused prep — weight transposes + pm-token prep in one launch.
// ---------------------------------------------------------------------------
__global__ __launch_bounds__(256) void prep_k(const float* __restrict__ Wq,
                                              const float* __restrict__ Wo,
                                              const float* __restrict__ pk,
                                              const float* __restrict__ pv,
                                              __half* __restrict__ Bq,
                                              __half* __restrict__ Bo,
                                              __half* kh, __half* kl, __half* vh) {
    if (blockIdx.z == 1 && blockIdx.x >= 32) {
        if (blockIdx.y != 0) return;
        int i = (blockIdx.x - 32) * 256 + threadIdx.x;
        if (i < HH * PP * DH) {
            float a = pk[i];
            __half h = __float2half_rn(a);
            kh[i] = h; kl[i] = __float2half_rn(a - __half2float(h));
            vh[i] = __float2half_rn(pv[i]);
        }
        return;
    }
    const float* W = (blockIdx.z == 0) ? Wq : Wo;
    __half* Bh = (blockIdx.z == 0) ? Bq : Bo;
    const int N = (blockIdx.z == 0) ? 3 * INNER : DD;
    const int K = (blockIdx.z == 0) ? DD : INNER;

    __shared__ float tile[32][33];
    int n0 = blockIdx.x * 32, k0 = blockIdx.y * 32;
    int tx = threadIdx.x & 31, ty = threadIdx.x >> 5;
    #pragma unroll
    for (int i = 0; i < 32; i += 8)
        tile[ty + i][tx] = W[(size_t)(k0 + ty + i) * N + n0 + tx];
    __syncthreads();
    #pragma unroll
    for (int i = 0; i < 32; i += 8) {
        float v = tile[tx][ty + i];
        Bh[(size_t)(n0 + ty + i) * K + k0 + tx] = __float2half_rn(v);
    }
}

// ---------------------------------------------------------------------------
// Kernel 3: HMMA fp16 GEMM, 1-term A (fp16) x fp16 B, runtime epilogue:
//   mode 1 (qkv): n0 < 2048 -> fp16 hi+lo epi; n0 >= 2048 -> fp16 hi only.
//   mode 0 (out-proj): fp32 epi.
// BK=64, 3-stage pipeline, 32KB stage (A | B), 96KB total.
// ---------------------------------------------------------------------------
#define TILEB   16384
#define NSTG    3
#define STGB    (2 * TILEB)
#define GSMEM   (NSTG * STGB)          // 96KB

__global__ __launch_bounds__(256, 1) void gemm_mma_k(const __half* __restrict__ Ah,
                                                     const __half* __restrict__ Bh,
                                                     float* __restrict__ C,
                                                     __half* __restrict__ Ch,
                                                     __half* __restrict__ Cl,
                                                     int Nld, int K, int mode) {
    extern __shared__ __align__(1024) char smem[];
    uint32_t sb = smem_u32(smem);
    const int tid = threadIdx.x;
    const int lane = tid & 31;
    const int wid = tid >> 5;
    const int m0 = blockIdx.y * 128, n0 = blockIdx.x * 128;
    const int wm = (wid & 1) * 64;
    const int wn = (wid >> 1) * 32;

    int epi;
    if (mode == 1) epi = (n0 < 2048) ? 1 : 2;
    else           epi = 0;

    float acc[4][4][4];
    #pragma unroll
    for (int i = 0; i < 4; i++)
        #pragma unroll
        for (int j = 0; j < 4; j++)
            #pragma unroll
            for (int r = 0; r < 4; r++) acc[i][j][r] = 0.0f;

    const int NC = K >> 6;             // BK = 64

    auto issue = [&](int c) {
        uint32_t base = sb + (c % NSTG) * STGB;
        #pragma unroll
        for (int tile = 0; tile < 2; ++tile) {
            const __half* gsrc = (tile == 0) ? Ah + (size_t)m0 * K + c * 64
                                             : Bh + (size_t)n0 * K + c * 64;
            #pragma unroll
            for (int it = 0; it < 4; ++it) {
                int lin = tid + it * 256;
                int r = lin >> 3, s = lin & 7;
                uint32_t dst = base + tile * TILEB + r * 128 + ((s ^ (r & 7)) << 4);
                const char* src = (const char*)(gsrc + (size_t)r * K + s * 8);
                CP_ASYNC16(dst, src);
            }
        }
        CP_COMMIT();
    };

    issue(0);
    if (NC > 1) issue(1);

    const int ra  = wm + (lane & 15);
    const int sa  = ra & 7;
    const int ha  = lane >> 4;
    const int rbl = (lane & 7) + ((lane >> 4) << 3);
    const int hb  = (lane >> 3) & 1;
    const int sbz = rbl & 7;

    for (int c = 0; c < NC; ++c) {
        if (c + 1 < NC) { CP_WAIT(1); }
        else            { CP_WAIT(0); }
        __syncthreads();
        if (c + 2 < NC) issue(c + 2);

        uint32_t base = sb + (c % NSTG) * STGB;
        uint32_t bbase = base + TILEB;
        #pragma unroll
        for (int ks = 0; ks < 4; ++ks) {
            const int kc = ks * 2;

            uint32_t aH[4][4];
            #pragma unroll
            for (int mt = 0; mt < 4; ++mt) {
                uint32_t ad = base + (ra + mt * 16) * 128 + (((kc + ha) ^ sa) << 4);
                LDSM4(aH[mt], ad);
            }
            uint32_t bH[4][2];
            #pragma unroll
            for (int np = 0; np < 2; ++np) {
                uint32_t t4[4];
                uint32_t ad = bbase + (wn + np * 16 + rbl) * 128
                            + (((kc + hb) ^ sbz) << 4);
                LDSM4(t4, ad);
                bH[np * 2][0] = t4[0]; bH[np * 2][1] = t4[1];
                bH[np * 2 + 1][0] = t4[2]; bH[np * 2 + 1][1] = t4[3];
            }
            #pragma unroll
            for (int mt = 0; mt < 4; ++mt)
                #pragma unroll
                for (int nt = 0; nt < 4; ++nt)
                    MMA_F16(acc[mt][nt], aH[mt], bH[nt]);
        }
    }

    #pragma unroll
    for (int mt = 0; mt < 4; ++mt) {
        #pragma unroll
        for (int nt = 0; nt < 4; ++nt) {
            int row = m0 + wm + mt * 16 + (lane >> 2);
            int col = n0 + wn + nt * 8 + (lane & 3) * 2;
            if (epi == 1) {
                uint32_t h0, l0, h1, l1;
                split2(acc[mt][nt][0], acc[mt][nt][1], h0, l0);
                split2(acc[mt][nt][2], acc[mt][nt][3], h1, l1);
                *reinterpret_cast<uint32_t*>(Ch + (size_t)row * Nld + col) = h0;
                *reinterpret_cast<uint32_t*>(Cl + (size_t)row * Nld + col) = l0;
                *reinterpret_cast<uint32_t*>(Ch + (size_t)(row + 8) * Nld + col) = h1;
                *reinterpret_cast<uint32_t*>(Cl + (size_t)(row + 8) * Nld + col) = l1;
            } else if (epi == 2) {
                *reinterpret_cast<uint32_t*>(Ch + (size_t)row * Nld + col) =
                    packh(acc[mt][nt][0], acc[mt][nt][1]);
                *reinterpret_cast<uint32_t*>(Ch + (size_t)(row + 8) * Nld + col) =
                    packh(acc[mt][nt][2], acc[mt][nt][3]);
            } else {
                *reinterpret_cast<float2*>(C + (size_t)row * Nld + col) =
                    make_float2(acc[mt][nt][0], acc[mt][nt][1]);
                *reinterpret_cast<float2*>(C + (size_t)(row + 8) * Nld + col) =
                    make_float2(acc[mt][nt][2], acc[mt][nt][3]);
            }
        }
    }
}

// ---------------------------------------------------------------------------
// Kernel 4: flash attention on mma.sync fp16.
// S: 3-term (Qh Kh + Qh Kl + Ql Kh).  PV: 2-term ((Ph+Pl) Vh).
// MMA issue interleaved across the two accumulator tiles (ILP; math-identical).
// ---------------------------------------------------------------------------
#define AT_QH   0
#define AT_QL   16384
#define AT_KV   32768
#define AT_KVB  24576          // 3 x 8KB
#define AT_SMEM (AT_KV + 2 * AT_KVB)   // 80KB

__global__ __launch_bounds__(256, 1) void attn_mma_k(const __half* __restrict__ qh,
                                                     const __half* __restrict__ ql,
                                                     const __half* __restrict__ pmkh,
                                                     const __half* __restrict__ pmkl,
                                                     const __half* __restrict__ pmvh,
                                                     __half* __restrict__ outh) {
    extern __shared__ __align__(1024) char smem[];
    uint32_t sb = smem_u32(smem);
    const int qt = 3 - blockIdx.x;         // heavy-first scheduling
    const int wh = blockIdx.y;
    const int b  = blockIdx.z;
    const int w  = wh >> 4;
    const int hd = wh & 15;
    const int tid = threadIdx.x;
    const int lane = tid & 31;
    const int wid = tid >> 5;
    const int tokbase = b * SS + w * SEGLEN;

    {
        #pragma unroll
        for (int t2 = 0; t2 < 2; ++t2) {
            const __half* src = t2 ? ql : qh;
            uint32_t dbase = sb + (t2 ? AT_QL : AT_QH);
            #pragma unroll
            for (int it = 0; it < 4; ++it) {
                int lin = tid + it * 256;
                int r = lin >> 3, s = lin & 7;
                CP_ASYNC16(dbase + r * 128 + ((s ^ (r & 7)) << 4),
                           src + (size_t)(tokbase + qt * 128 + r) * 3072 + hd * 64 + s * 8);
            }
        }
        CP_COMMIT();
    }

    const int nch = ((qt * 128 + 127 + PP) >> 6) + 1;

    auto stage = [&](int c, int buf) {
        int c0 = c * 64;
        uint32_t base = sb + AT_KV + buf * AT_KVB;
        #pragma unroll
        for (int tile = 0; tile < 3; ++tile) {
            const __half* pmsrc = (tile == 0) ? pmkh : (tile == 1) ? pmkl : pmvh;
            const __half* tsrc  = (tile == 1) ? ql : qh;
            const int toff = (tile < 2) ? 1024 : 2048;
            #pragma unroll
            for (int it = 0; it < 2; ++it) {
                int lin = tid + it * 256;
                int r = lin >> 3, s = lin & 7;
                int j = c0 + r;
                uint32_t dst = base + tile * 8192 + r * 128 + ((s ^ (r & 7)) << 4);
                if (j < PP) {
                    CP_ASYNC16(dst, pmsrc + (hd * PP + j) * 64 + s * 8);
                } else if (j < TOTKEY) {
                    CP_ASYNC16(dst, tsrc + (size_t)(tokbase + j - PP) * 3072 + toff + hd * 64 + s * 8);
                } else {
                    uint4 z = make_uint4(0, 0, 0, 0);
                    *reinterpret_cast<uint4*>(smem + (dst - sb)) = z;
                }
            }
        }
        CP_COMMIT();
    };

    stage(0, 0);
    CP_WAIT(0);
    __syncthreads();

    uint32_t qfh[4][4], qfl[4][4];
    const int ra = wid * 16 + (lane & 15);
    const int ha = lane >> 4;
    #pragma unroll
    for (int ks = 0; ks < 4; ++ks) {
        uint32_t ad = sb + AT_QH + ra * 128 + (((ks * 2 + ha) ^ (ra & 7)) << 4);
        LDSM4(qfh[ks], ad);
        LDSM4(qfl[ks], ad + AT_QL);
    }

    const int lr = lane >> 2;
    const int i0 = qt * 128 + wid * 16 + lr;
    const int i1 = i0 + 8;
    float m0 = -1e30f, m1 = -1e30f, l0 = 0.0f, l1 = 0.0f;
    float oacc[8][4];
    #pragma unroll
    for (int d = 0; d < 8; ++d)
        #pragma unroll
        for (int r = 0; r < 4; ++r) oacc[d][r] = 0.0f;

    const int rbl = (lane & 7) + ((lane >> 4) << 3);
    const int hb  = (lane >> 3) & 1;
    const int sbz = rbl & 7;
    const int vrow = lane & 15;
    const int vhi  = lane >> 4;

    for (int c = 0; c < nch; ++c) {
        if (c + 1 < nch) { stage(c + 1, (c + 1) & 1); CP_WAIT(1); }
        else            { CP_WAIT(0); }
        __syncthreads();

        uint32_t kb = sb + AT_KV + (c & 1) * AT_KVB;
        uint32_t vb = kb + 2 * 8192;
        int c0 = c * 64;

        float sacc[8][4];
        #pragma unroll
        for (int n = 0; n < 8; ++n)
            #pragma unroll
            for (int r = 0; r < 4; ++r) sacc[n][r] = 0.0f;

        #pragma unroll
        for (int ks = 0; ks < 4; ++ks) {
            #pragma unroll
            for (int np = 0; np < 4; ++np) {
                uint32_t kh4[4], kl4[4];
                uint32_t ad = kb + (np * 16 + rbl) * 128 + (((ks * 2 + hb) ^ sbz) << 4);
                LDSM4(kh4, ad);
                LDSM4(kl4, ad + 8192);
                // interleaved across the two accumulators (dep distance 2)
                MMA_F16(sacc[2 * np],     qfh[ks], (&kh4[0]));
                MMA_F16(sacc[2 * np + 1], qfh[ks], (&kh4[2]));
                MMA_F16(sacc[2 * np],     qfh[ks], (&kl4[0]));
                MMA_F16(sacc[2 * np + 1], qfh[ks], (&kl4[2]));
                MMA_F16(sacc[2 * np],     qfl[ks], (&kh4[0]));
                MMA_F16(sacc[2 * np + 1], qfl[ks], (&kh4[2]));
            }
        }

        const float sc = 0.125f;
        float rm0 = -1e30f, rm1 = -1e30f;
        #pragma unroll
        for (int n = 0; n < 8; ++n) {
            int jb = c0 + n * 8 + (lane & 3) * 2;
            #pragma unroll
            for (int r = 0; r < 4; ++r) {
                int j = jb + (r & 1);
                int i = (r < 2) ? i0 : i1;
                bool valid = (j < PP) | (i + PP >= j);
                float z = valid ? sacc[n][r] * sc : -1e30f;
                sacc[n][r] = z;
                if (r < 2) rm0 = fmaxf(rm0, z); else rm1 = fmaxf(rm1, z);
            }
        }
        rm0 = fmaxf(rm0, __shfl_xor_sync(0xffffffffu, rm0, 1));
        rm0 = fmaxf(rm0, __shfl_xor_sync(0xffffffffu, rm0, 2));
        rm1 = fmaxf(rm1, __shfl_xor_sync(0xffffffffu, rm1, 1));
        rm1 = fmaxf(rm1, __shfl_xor_sync(0xffffffffu, rm1, 2));

        float mn0 = fmaxf(m0, rm0), mn1 = fmaxf(m1, rm1);
        float corr0 = __expf(m0 - mn0), corr1 = __expf(m1 - mn1);
        m0 = mn0; m1 = mn1;

        float rs0 = 0.0f, rs1 = 0.0f;
        #pragma unroll
        for (int n = 0; n < 8; ++n) {
            float p0 = __expf(sacc[n][0] - m0);
            float p1 = __expf(sacc[n][1] - m0);
            float p2 = __expf(sacc[n][2] - m1);
            float p3 = __expf(sacc[n][3] - m1);
            sacc[n][0] = p0; sacc[n][1] = p1; sacc[n][2] = p2; sacc[n][3] = p3;
            rs0 += p0 + p1; rs1 += p2 + p3;
        }
        rs0 += __shfl_xor_sync(0xffffffffu, rs0, 1);
        rs0 += __shfl_xor_sync(0xffffffffu, rs0, 2);
        rs1 += __shfl_xor_sync(0xffffffffu, rs1, 1);
        rs1 += __shfl_xor_sync(0xffffffffu, rs1, 2);
        l0 = l0 * corr0 + rs0;
        l1 = l1 * corr1 + rs1;

        #pragma unroll
        for (int d = 0; d < 8; ++d) {
            oacc[d][0] *= corr0; oacc[d][1] *= corr0;
            oacc[d][2] *= corr1; oacc[d][3] *= corr1;
        }

        #pragma unroll
        for (int ks = 0; ks < 4; ++ks) {
            uint32_t pah[4], pal[4];
            split2(sacc[2 * ks][0],     sacc[2 * ks][1],     pah[0], pal[0]);
            split2(sacc[2 * ks][2],     sacc[2 * ks][3],     pah[1], pal[1]);
            split2(sacc[2 * ks + 1][0], sacc[2 * ks + 1][1], pah[2], pal[2]);
            split2(sacc[2 * ks + 1][2], sacc[2 * ks + 1][3], pah[3], pal[3]);

            #pragma unroll
            for (int dt2 = 0; dt2 < 4; ++dt2) {
                int krow = ks * 16 + vrow;
                uint32_t ad = vb + krow * 128 + (((dt2 * 2 + vhi) ^ (krow & 7)) << 4);
                uint32_t vh4[4];
                LDSM4T(vh4, ad);
                // interleaved across the two accumulators (dep distance 2)
                MMA_F16(oacc[2 * dt2],     pah, (&vh4[0]));
                MMA_F16(oacc[2 * dt2 + 1], pah, (&vh4[2]));
                MMA_F16(oacc[2 * dt2],     pal, (&vh4[0]));
                MMA_F16(oacc[2 * dt2 + 1], pal, (&vh4[2]));
            }
        }
        __syncthreads();
    }

    float il0 = 1.0f / l0, il1 = 1.0f / l1;
    size_t tok0 = (size_t)tokbase + i0;
    size_t tok1 = (size_t)tokbase + i1;
    #pragma unroll
    for (int d = 0; d < 8; ++d) {
        int col = hd * 64 + d * 8 + (lane & 3) * 2;
        *reinterpret_cast<uint32_t*>(outh + tok0 * 1024 + col) =
            packh(oacc[d][0] * il0, oacc[d][1] * il0);
        *reinterpret_cast<uint32_t*>(outh + tok1 * 1024 + col) =
            packh(oacc[d][2] * il1, oacc[d][3] * il1);
    }
}

// ---------------------------------------------------------------------------
extern "C" void kernel_launch(void* const* d_in, const int* in_sizes, int n_in,
                              void* d_out, int out_size) {
    const float* x     = (const float*)d_in[0];
    const float* gamma = (const float*)d_in[1];
    const float* w_qkv = (const float*)d_in[2];
    const float* w_out = (const float*)d_in[3];
    const float* pm_k  = (const float*)d_in[4];
    const float* pm_v  = (const float*)d_in[5];
    float* out = (float*)d_out;

    __half *qh, *ql, *ah, *ch, *bhq, *bho;
    __half *pmkh, *pmkl, *pmvh;
    cudaGetSymbolAddress((void**)&qh,  g_qh);
    cudaGetSymbolAddress((void**)&ql,  g_ql);
    cudaGetSymbolAddress((void**)&ah,  g_ah);
    cudaGetSymbolAddress((void**)&ch,  g_ch);
    cudaGetSymbolAddress((void**)&bhq, g_bhq);
    cudaGetSymbolAddress((void**)&bho, g_bho);
    cudaGetSymbolAddress((void**)&pmkh, g_pmkh);
    cudaGetSymbolAddress((void**)&pmkl, g_pmkl);
    cudaGetSymbolAddress((void**)&pmvh, g_pmvh);

    cudaFuncSetAttribute(gemm_mma_k, cudaFuncAttributeMaxDynamicSharedMemorySize, GSMEM);
    cudaFuncSetAttribute(attn_mma_k, cudaFuncAttributeMaxDynamicSharedMemorySize, AT_SMEM);

    // 1) RMSNorm -> fp16
    rmsnorm_split_k<<<NTOK, 256>>>(x, gamma, ah);

    // 2) fused prep: both weight transposes + pm tokens in one launch
    prep_k<<<dim3(96, 32, 2), 256>>>(w_qkv, w_out, pm_k, pm_v,
                                     bhq, bho, pmkh, pmkl, pmvh);

    // 3) QKV projection (1-term A): x<16 -> QK (hi+lo epi); x>=16 -> V (hi epi)
    gemm_mma_k<<<dim3(24, NTOK / 128), 256, GSMEM>>>(
        ah, bhq, nullptr, qh, ql, 3 * INNER, DD, /*mode=*/1);

    // 4) attention on tensor cores (3-term S, 2-term PV), heavy-first
    attn_mma_k<<<dim3(SEGLEN / 128, NWIN * HH, BB), 256, AT_SMEM>>>(
        qh, ql, pmkh, pmkl, pmvh, ch);

    // 5) output projection (1-term) -> fp32
    gemm_mma_k<<<dim3(DD / 128, NTOK / 128), 256, GSMEM>>>(
        ch, bho, out, nullptr, nullptr, INNER, INNER, /*mode=*/0);
}

// round 16
// speedup vs baseline: 1.5087x; 1.5087x over previous
#include <cuda_runtime.h>
#include <cuda_fp16.h>
#include <math.h>
#include <stdint.h>

#define BB     2
#define SS     4096
#define DD     1024
#define HH     16
#define DH     64
#define SEGLEN 512
#define PP     16
#define NWIN   8
#define INNER  1024
#define NTOK   (BB * SS)   // 8192
#define TOTKEY (SEGLEN + PP)  // 528

// ---------------- scratch (device globals; no allocation allowed) ----------
__device__ __half  g_qh[NTOK * 3 * INNER];      // qkv hi plane
__device__ __half  g_ql[NTOK * 3 * INNER];      // qkv lo plane (V cols unused)
__device__ __half  g_ah[NTOK * DD];             // rmsnorm out (fp16, single plane)
__device__ __half  g_ch[NTOK * INNER];          // attn out (fp16, single plane)
__device__ __half  g_bhq[3 * INNER * DD];       // w_qkv^T fp16  [N,K]
__device__ __half  g_bho[DD * INNER];           // w_out^T fp16  [N,K]
__device__ __half  g_pmkh[HH * PP * DH];        // pm_k hi
__device__ __half  g_pmkl[HH * PP * DH];
__device__ __half  g_pmvh[HH * PP * DH];        // pm_v (fp16 single)

// ---------------- PTX helpers (sm_80-class only; no 'a'-features) ----------
__device__ __forceinline__ uint32_t smem_u32(const void* p) {
    uint32_t a;
    asm("{ .reg .u64 t; cvta.to.shared.u64 t, %1; cvt.u32.u64 %0, t; }" : "=r"(a) : "l"(p));
    return a;
}

#define CP_ASYNC16(saddr, gptr) \
    asm volatile("cp.async.cg.shared.global [%0], [%1], 16;" :: "r"(saddr), "l"(gptr))
#define CP_COMMIT() asm volatile("cp.async.commit_group;" ::: "memory")
#define CP_WAIT(n)  asm volatile("cp.async.wait_group %0;" :: "n"(n) : "memory")

#define LDSM4(r, a)                                                                 \
    asm volatile("ldmatrix.sync.aligned.m8n8.x4.shared.b16 {%0,%1,%2,%3}, [%4];"    \
        : "=r"((r)[0]), "=r"((r)[1]), "=r"((r)[2]), "=r"((r)[3]) : "r"(a))

#define LDSM4T(r, a)                                                                \
    asm volatile("ldmatrix.sync.aligned.m8n8.x4.trans.shared.b16 {%0,%1,%2,%3}, [%4];" \
        : "=r"((r)[0]), "=r"((r)[1]), "=r"((r)[2]), "=r"((r)[3]) : "r"(a))

#define MMA_F16(d, a, b)                                                            \
    asm volatile("mma.sync.aligned.m16n8k16.row.col.f32.f16.f16.f32 "               \
        "{%0,%1,%2,%3}, {%4,%5,%6,%7}, {%8,%9}, {%0,%1,%2,%3};"                     \
        : "+f"((d)[0]), "+f"((d)[1]), "+f"((d)[2]), "+f"((d)[3])                    \
        : "r"((a)[0]), "r"((a)[1]), "r"((a)[2]), "r"((a)[3]), "r"((b)[0]), "r"((b)[1]))

__device__ __forceinline__ uint32_t packh(float x, float y) {
    __half2 t = __floats2half2_rn(x, y);
    return *reinterpret_cast<uint32_t*>(&t);
}
__device__ __forceinline__ void split2(float x, float y, uint32_t& ph, uint32_t& pl) {
    __half hx = __float2half_rn(x), hy = __float2half_rn(y);
    __half2 hp = __halves2half2(hx, hy);
    ph = *reinterpret_cast<uint32_t*>(&hp);
    pl = packh(x - __half2float(hx), y - __half2float(hy));
}

// ---------------------------------------------------------------------------
// Kernel 1: RMSNorm -> single fp16 plane.
// ---------------------------------------------------------------------------
__global__ __launch_bounds__(256) void rmsnorm_split_k(const float* __restrict__ x,
                                                       const float* __restrict__ gamma,
                                                       __half* __restrict__ Ah) {
    int row = blockIdx.x;
    int t = threadIdx.x;
    const float4* xr = reinterpret_cast<const float4*>(x + (size_t)row * DD);
    const float4* gr = reinterpret_cast<const float4*>(gamma);

    float4 v = xr[t];
    float ss = v.x * v.x + v.y * v.y + v.z * v.z + v.w * v.w;
    #pragma unroll
    for (int o = 16; o > 0; o >>= 1) ss += __shfl_xor_sync(0xffffffffu, ss, o);

    __shared__ float red[8];
    int warp = t >> 5, lane = t & 31;
    if (lane == 0) red[warp] = ss;
    __syncthreads();
    if (warp == 0) {
        float s2 = (lane < 8) ? red[lane] : 0.0f;
        #pragma unroll
        for (int o = 16; o > 0; o >>= 1) s2 += __shfl_xor_sync(0xffffffffu, s2, o);
        if (lane == 0) red[0] = s2;
    }
    __syncthreads();

    float inv = rsqrtf(red[0] * (1.0f / DD) + 1e-6f);
    float4 g = gr[t];
    uint2 hi;
    hi.x = packh(v.x * inv * g.x, v.y * inv * g.y);
    hi.y = packh(v.z * inv * g.z, v.w * inv * g.w);
    *reinterpret_cast<uint2*>(Ah + (size_t)row * DD + t * 4) = hi;
}

// ---------------------------------------------------------------------------
// Kernel 2: fused prep — weight transposes + pm-token prep in one launch.
// ---------------------------------------------------------------------------
__global__ __launch_bounds__(256) void prep_k(const float* __restrict__ Wq,
                                              const float* __restrict__ Wo,
                                              const float* __restrict__ pk,
                                              const float* __restrict__ pv,
                                              __half* __restrict__ Bq,
                                              __half* __restrict__ Bo,
                                              __half* kh, __half* kl, __half* vh) {
    if (blockIdx.z == 1 && blockIdx.x >= 32) {
        if (blockIdx.y != 0) return;
        int i = (blockIdx.x - 32) * 256 + threadIdx.x;
        if (i < HH * PP * DH) {
            float a = pk[i];
            __half h = __float2half_rn(a);
            kh[i] = h; kl[i] = __float2half_rn(a - __half2float(h));
            vh[i] = __float2half_rn(pv[i]);
        }
        return;
    }
    const float* W = (blockIdx.z == 0) ? Wq : Wo;
    __half* Bh = (blockIdx.z == 0) ? Bq : Bo;
    const int N = (blockIdx.z == 0) ? 3 * INNER : DD;
    const int K = (blockIdx.z == 0) ? DD : INNER;

    __shared__ float tile[32][33];
    int n0 = blockIdx.x * 32, k0 = blockIdx.y * 32;
    int tx = threadIdx.x & 31, ty = threadIdx.x >> 5;
    #pragma unroll
    for (int i = 0; i < 32; i += 8)
        tile[ty + i][tx] = W[(size_t)(k0 + ty + i) * N + n0 + tx];
    __syncthreads();
    #pragma unroll
    for (int i = 0; i < 32; i += 8) {
        float v = tile[tx][ty + i];
        Bh[(size_t)(n0 + ty + i) * K + k0 + tx] = __float2half_rn(v);
    }
}

// ---------------------------------------------------------------------------
// Kernel 3: HMMA fp16 GEMM, 1-term A (fp16) x fp16 B, runtime epilogue:
//   mode 1 (qkv): n0 < 2048 -> fp16 hi+lo epi; n0 >= 2048 -> fp16 hi only.
//   mode 0 (out-proj): fp32 epi.
// BK=64, 3-stage pipeline, 32KB stage (A | B), 96KB total.
// ---------------------------------------------------------------------------
#define TILEB   16384
#define NSTG    3
#define STGB    (2 * TILEB)
#define GSMEM   (NSTG * STGB)          // 96KB

__global__ __launch_bounds__(256, 1) void gemm_mma_k(const __half* __restrict__ Ah,
                                                     const __half* __restrict__ Bh,
                                                     float* __restrict__ C,
                                                     __half* __restrict__ Ch,
                                                     __half* __restrict__ Cl,
                                                     int Nld, int K, int mode) {
    extern __shared__ __align__(1024) char smem[];
    uint32_t sb = smem_u32(smem);
    const int tid = threadIdx.x;
    const int lane = tid & 31;
    const int wid = tid >> 5;
    const int m0 = blockIdx.y * 128, n0 = blockIdx.x * 128;
    const int wm = (wid & 1) * 64;
    const int wn = (wid >> 1) * 32;

    int epi;
    if (mode == 1) epi = (n0 < 2048) ? 1 : 2;
    else           epi = 0;

    float acc[4][4][4];
    #pragma unroll
    for (int i = 0; i < 4; i++)
        #pragma unroll
        for (int j = 0; j < 4; j++)
            #pragma unroll
            for (int r = 0; r < 4; r++) acc[i][j][r] = 0.0f;

    const int NC = K >> 6;             // BK = 64

    auto issue = [&](int c) {
        uint32_t base = sb + (c % NSTG) * STGB;
        #pragma unroll
        for (int tile = 0; tile < 2; ++tile) {
            const __half* gsrc = (tile == 0) ? Ah + (size_t)m0 * K + c * 64
                                             : Bh + (size_t)n0 * K + c * 64;
            #pragma unroll
            for (int it = 0; it < 4; ++it) {
                int lin = tid + it * 256;
                int r = lin >> 3, s = lin & 7;
                uint32_t dst = base + tile * TILEB + r * 128 + ((s ^ (r & 7)) << 4);
                const char* src = (const char*)(gsrc + (size_t)r * K + s * 8);
                CP_ASYNC16(dst, src);
            }
        }
        CP_COMMIT();
    };

    issue(0);
    if (NC > 1) issue(1);

    const int ra  = wm + (lane & 15);
    const int sa  = ra & 7;
    const int ha  = lane >> 4;
    const int rbl = (lane & 7) + ((lane >> 4) << 3);
    const int hb  = (lane >> 3) & 1;
    const int sbz = rbl & 7;

    for (int c = 0; c < NC; ++c) {
        if (c + 1 < NC) { CP_WAIT(1); }
        else            { CP_WAIT(0); }
        __syncthreads();
        if (c + 2 < NC) issue(c + 2);

        uint32_t base = sb + (c % NSTG) * STGB;
        uint32_t bbase = base + TILEB;
        #pragma unroll
        for (int ks = 0; ks < 4; ++ks) {
            const int kc = ks * 2;

            uint32_t aH[4][4];
            #pragma unroll
            for (int mt = 0; mt < 4; ++mt) {
                uint32_t ad = base + (ra + mt * 16) * 128 + (((kc + ha) ^ sa) << 4);
                LDSM4(aH[mt], ad);
            }
            uint32_t bH[4][2];
            #pragma unroll
            for (int np = 0; np < 2; ++np) {
                uint32_t t4[4];
                uint32_t ad = bbase + (wn + np * 16 + rbl) * 128
                            + (((kc + hb) ^ sbz) << 4);
                LDSM4(t4, ad);
                bH[np * 2][0] = t4[0]; bH[np * 2][1] = t4[1];
                bH[np * 2 + 1][0] = t4[2]; bH[np * 2 + 1][1] = t4[3];
            }
            #pragma unroll
            for (int mt = 0; mt < 4; ++mt)
                #pragma unroll
                for (int nt = 0; nt < 4; ++nt)
                    MMA_F16(acc[mt][nt], aH[mt], bH[nt]);
        }
    }

    #pragma unroll
    for (int mt = 0; mt < 4; ++mt) {
        #pragma unroll
        for (int nt = 0; nt < 4; ++nt) {
            int row = m0 + wm + mt * 16 + (lane >> 2);
            int col = n0 + wn + nt * 8 + (lane & 3) * 2;
            if (epi == 1) {
                uint32_t h0, l0, h1, l1;
                split2(acc[mt][nt][0], acc[mt][nt][1], h0, l0);
                split2(acc[mt][nt][2], acc[mt][nt][3], h1, l1);
                *reinterpret_cast<uint32_t*>(Ch + (size_t)row * Nld + col) = h0;
                *reinterpret_cast<uint32_t*>(Cl + (size_t)row * Nld + col) = l0;
                *reinterpret_cast<uint32_t*>(Ch + (size_t)(row + 8) * Nld + col) = h1;
                *reinterpret_cast<uint32_t*>(Cl + (size_t)(row + 8) * Nld + col) = l1;
            } else if (epi == 2) {
                *reinterpret_cast<uint32_t*>(Ch + (size_t)row * Nld + col) =
                    packh(acc[mt][nt][0], acc[mt][nt][1]);
                *reinterpret_cast<uint32_t*>(Ch + (size_t)(row + 8) * Nld + col) =
                    packh(acc[mt][nt][2], acc[mt][nt][3]);
            } else {
                *reinterpret_cast<float2*>(C + (size_t)row * Nld + col) =
                    make_float2(acc[mt][nt][0], acc[mt][nt][1]);
                *reinterpret_cast<float2*>(C + (size_t)(row + 8) * Nld + col) =
                    make_float2(acc[mt][nt][2], acc[mt][nt][3]);
            }
        }
    }
}

// ---------------------------------------------------------------------------
// Kernel 4: flash attention on mma.sync fp16 — R13 MMA grouping (proven 113us).
// S: 3-term (Qh Kh + Qh Kl + Ql Kh).  PV: 2-term ((Ph+Pl) Vh).
// ---------------------------------------------------------------------------
#define AT_QH   0
#define AT_QL   16384
#define AT_KV   32768
#define AT_KVB  24576          // 3 x 8KB
#define AT_SMEM (AT_KV + 2 * AT_KVB)   // 80KB

__global__ __launch_bounds__(256, 1) void attn_mma_k(const __half* __restrict__ qh,
                                                     const __half* __restrict__ ql,
                                                     const __half* __restrict__ pmkh,
                                                     const __half* __restrict__ pmkl,
                                                     const __half* __restrict__ pmvh,
                                                     __half* __restrict__ outh) {
    extern __shared__ __align__(1024) char smem[];
    uint32_t sb = smem_u32(smem);
    const int qt = 3 - blockIdx.x;         // heavy-first scheduling
    const int wh = blockIdx.y;
    const int b  = blockIdx.z;
    const int w  = wh >> 4;
    const int hd = wh & 15;
    const int tid = threadIdx.x;
    const int lane = tid & 31;
    const int wid = tid >> 5;
    const int tokbase = b * SS + w * SEGLEN;

    {
        #pragma unroll
        for (int t2 = 0; t2 < 2; ++t2) {
            const __half* src = t2 ? ql : qh;
            uint32_t dbase = sb + (t2 ? AT_QL : AT_QH);
            #pragma unroll
            for (int it = 0; it < 4; ++it) {
                int lin = tid + it * 256;
                int r = lin >> 3, s = lin & 7;
                CP_ASYNC16(dbase + r * 128 + ((s ^ (r & 7)) << 4),
                           src + (size_t)(tokbase + qt * 128 + r) * 3072 + hd * 64 + s * 8);
            }
        }
        CP_COMMIT();
    }

    const int nch = ((qt * 128 + 127 + PP) >> 6) + 1;

    auto stage = [&](int c, int buf) {
        int c0 = c * 64;
        uint32_t base = sb + AT_KV + buf * AT_KVB;
        #pragma unroll
        for (int tile = 0; tile < 3; ++tile) {
            const __half* pmsrc = (tile == 0) ? pmkh : (tile == 1) ? pmkl : pmvh;
            const __half* tsrc  = (tile == 1) ? ql : qh;
            const int toff = (tile < 2) ? 1024 : 2048;
            #pragma unroll
            for (int it = 0; it < 2; ++it) {
                int lin = tid + it * 256;
                int r = lin >> 3, s = lin & 7;
                int j = c0 + r;
                uint32_t dst = base + tile * 8192 + r * 128 + ((s ^ (r & 7)) << 4);
                if (j < PP) {
                    CP_ASYNC16(dst, pmsrc + (hd * PP + j) * 64 + s * 8);
                } else if (j < TOTKEY) {
                    CP_ASYNC16(dst, tsrc + (size_t)(tokbase + j - PP) * 3072 + toff + hd * 64 + s * 8);
                } else {
                    uint4 z = make_uint4(0, 0, 0, 0);
                    *reinterpret_cast<uint4*>(smem + (dst - sb)) = z;
                }
            }
        }
        CP_COMMIT();
    };

    stage(0, 0);
    CP_WAIT(0);
    __syncthreads();

    uint32_t qfh[4][4], qfl[4][4];
    const int ra = wid * 16 + (lane & 15);
    const int ha = lane >> 4;
    #pragma unroll
    for (int ks = 0; ks < 4; ++ks) {
        uint32_t ad = sb + AT_QH + ra * 128 + (((ks * 2 + ha) ^ (ra & 7)) << 4);
        LDSM4(qfh[ks], ad);
        LDSM4(qfl[ks], ad + AT_QL);
    }

    const int lr = lane >> 2;
    const int i0 = qt * 128 + wid * 16 + lr;
    const int i1 = i0 + 8;
    float m0 = -1e30f, m1 = -1e30f, l0 = 0.0f, l1 = 0.0f;
    float oacc[8][4];
    #pragma unroll
    for (int d = 0; d < 8; ++d)
        #pragma unroll
        for (int r = 0; r < 4; ++r) oacc[d][r] = 0.0f;

    const int rbl = (lane & 7) + ((lane >> 4) << 3);
    const int hb  = (lane >> 3) & 1;
    const int sbz = rbl & 7;
    const int vrow = lane & 15;
    const int vhi  = lane >> 4;

    for (int c = 0; c < nch; ++c) {
        if (c + 1 < nch) { stage(c + 1, (c + 1) & 1); CP_WAIT(1); }
        else            { CP_WAIT(0); }
        __syncthreads();

        uint32_t kb = sb + AT_KV + (c & 1) * AT_KVB;
        uint32_t vb = kb + 2 * 8192;
        int c0 = c * 64;

        float sacc[8][4];
        #pragma unroll
        for (int n = 0; n < 8; ++n)
            #pragma unroll
            for (int r = 0; r < 4; ++r) sacc[n][r] = 0.0f;

        #pragma unroll
        for (int ks = 0; ks < 4; ++ks) {
            #pragma unroll
            for (int np = 0; np < 4; ++np) {
                uint32_t kh4[4], kl4[4];
                uint32_t ad = kb + (np * 16 + rbl) * 128 + (((ks * 2 + hb) ^ sbz) << 4);
                LDSM4(kh4, ad);
                LDSM4(kl4, ad + 8192);
                MMA_F16(sacc[2 * np],     qfh[ks], (&kh4[0]));
                MMA_F16(sacc[2 * np],     qfh[ks], (&kl4[0]));
                MMA_F16(sacc[2 * np],     qfl[ks], (&kh4[0]));
                MMA_F16(sacc[2 * np + 1], qfh[ks], (&kh4[2]));
                MMA_F16(sacc[2 * np + 1], qfh[ks], (&kl4[2]));
                MMA_F16(sacc[2 * np + 1], qfl[ks], (&kh4[2]));
            }
        }

        const float sc = 0.125f;
        float rm0 = -1e30f, rm1 = -1e30f;
        #pragma unroll
        for (int n = 0; n < 8; ++n) {
            int jb = c0 + n * 8 + (lane & 3) * 2;
            #pragma unroll
            for (int r = 0; r < 4; ++r) {
                int j = jb + (r & 1);
                int i = (r < 2) ? i0 : i1;
                bool valid = (j < PP) | (i + PP >= j);
                float z = valid ? sacc[n][r] * sc : -1e30f;
                sacc[n][r] = z;
                if (r < 2) rm0 = fmaxf(rm0, z); else rm1 = fmaxf(rm1, z);
            }
        }
        rm0 = fmaxf(rm0, __shfl_xor_sync(0xffffffffu, rm0, 1));
        rm0 = fmaxf(rm0, __shfl_xor_sync(0xffffffffu, rm0, 2));
        rm1 = fmaxf(rm1, __shfl_xor_sync(0xffffffffu, rm1, 1));
        rm1 = fmaxf(rm1, __shfl_xor_sync(0xffffffffu, rm1, 2));

        float mn0 = fmaxf(m0, rm0), mn1 = fmaxf(m1, rm1);
        float corr0 = __expf(m0 - mn0), corr1 = __expf(m1 - mn1);
        m0 = mn0; m1 = mn1;

        float rs0 = 0.0f, rs1 = 0.0f;
        #pragma unroll
        for (int n = 0; n < 8; ++n) {
            float p0 = __expf(sacc[n][0] - m0);
            float p1 = __expf(sacc[n][1] - m0);
            float p2 = __expf(sacc[n][2] - m1);
            float p3 = __expf(sacc[n][3] - m1);
            sacc[n][0] = p0; sacc[n][1] = p1; sacc[n][2] = p2; sacc[n][3] = p3;
            rs0 += p0 + p1; rs1 += p2 + p3;
        }
        rs0 += __shfl_xor_sync(0xffffffffu, rs0, 1);
        rs0 += __shfl_xor_sync(0xffffffffu, rs0, 2);
        rs1 += __shfl_xor_sync(0xffffffffu, rs1, 1);
        rs1 += __shfl_xor_sync(0xffffffffu, rs1, 2);
        l0 = l0 * corr0 + rs0;
        l1 = l1 * corr1 + rs1;

        #pragma unroll
        for (int d = 0; d < 8; ++d) {
            oacc[d][0] *= corr0; oacc[d][1] *= corr0;
            oacc[d][2] *= corr1; oacc[d][3] *= corr1;
        }

        #pragma unroll
        for (int ks = 0; ks < 4; ++ks) {
            uint32_t pah[4], pal[4];
            split2(sacc[2 * ks][0],     sacc[2 * ks][1],     pah[0], pal[0]);
            split2(sacc[2 * ks][2],     sacc[2 * ks][3],     pah[1], pal[1]);
            split2(sacc[2 * ks + 1][0], sacc[2 * ks + 1][1], pah[2], pal[2]);
            split2(sacc[2 * ks + 1][2], sacc[2 * ks + 1][3], pah[3], pal[3]);

            #pragma unroll
            for (int dt2 = 0; dt2 < 4; ++dt2) {
                int krow = ks * 16 + vrow;
                uint32_t ad = vb + krow * 128 + (((dt2 * 2 + vhi) ^ (krow & 7)) << 4);
                uint32_t vh4[4];
                LDSM4T(vh4, ad);
                MMA_F16(oacc[2 * dt2],     pah, (&vh4[0]));
                MMA_F16(oacc[2 * dt2],     pal, (&vh4[0]));
                MMA_F16(oacc[2 * dt2 + 1], pah, (&vh4[2]));
                MMA_F16(oacc[2 * dt2 + 1], pal, (&vh4[2]));
            }
        }
        __syncthreads();
    }

    float il0 = 1.0f / l0, il1 = 1.0f / l1;
    size_t tok0 = (size_t)tokbase + i0;
    size_t tok1 = (size_t)tokbase + i1;
    #pragma unroll
    for (int d = 0; d < 8; ++d) {
        int col = hd * 64 + d * 8 + (lane & 3) * 2;
        *reinterpret_cast<uint32_t*>(outh + tok0 * 1024 + col) =
            packh(oacc[d][0] * il0, oacc[d][1] * il0);
        *reinterpret_cast<uint32_t*>(outh + tok1 * 1024 + col) =
            packh(oacc[d][2] * il1, oacc[d][3] * il1);
    }
}

// ---------------------------------------------------------------------------
extern "C" void kernel_launch(void* const* d_in, const int* in_sizes, int n_in,
                              void* d_out, int out_size) {
    const float* x     = (const float*)d_in[0];
    const float* gamma = (const float*)d_in[1];
    const float* w_qkv = (const float*)d_in[2];
    const float* w_out = (const float*)d_in[3];
    const float* pm_k  = (const float*)d_in[4];
    const float* pm_v  = (const float*)d_in[5];
    float* out = (float*)d_out;

    __half *qh, *ql, *ah, *ch, *bhq, *bho;
    __half *pmkh, *pmkl, *pmvh;
    cudaGetSymbolAddress((void**)&qh,  g_qh);
    cudaGetSymbolAddress((void**)&ql,  g_ql);
    cudaGetSymbolAddress((void**)&ah,  g_ah);
    cudaGetSymbolAddress((void**)&ch,  g_ch);
    cudaGetSymbolAddress((void**)&bhq, g_bhq);
    cudaGetSymbolAddress((void**)&bho, g_bho);
    cudaGetSymbolAddress((void**)&pmkh, g_pmkh);
    cudaGetSymbolAddress((void**)&pmkl, g_pmkl);
    cudaGetSymbolAddress((void**)&pmvh, g_pmvh);

    cudaFuncSetAttribute(gemm_mma_k, cudaFuncAttributeMaxDynamicSharedMemorySize, GSMEM);
    cudaFuncSetAttribute(attn_mma_k, cudaFuncAttributeMaxDynamicSharedMemorySize, AT_SMEM);

    // 1) RMSNorm -> fp16
    rmsnorm_split_k<<<NTOK, 256>>>(x, gamma, ah);

    // 2) fused prep: both weight transposes + pm tokens in one launch
    prep_k<<<dim3(96, 32, 2), 256>>>(w_qkv, w_out, pm_k, pm_v,
                                     bhq, bho, pmkh, pmkl, pmvh);

    // 3) QKV projection (1-term A): x<16 -> QK (hi+lo epi); x>=16 -> V (hi epi)
    gemm_mma_k<<<dim3(24, NTOK / 128), 256, GSMEM>>>(
        ah, bhq, nullptr, qh, ql, 3 * INNER, DD, /*mode=*/1);

    // 4) attention on tensor cores (3-term S, 2-term PV), heavy-first
    attn_mma_k<<<dim3(SEGLEN / 128, NWIN * HH, BB), 256, AT_SMEM>>>(
        qh, ql, pmkh, pmkl, pmvh, ch);

    // 5) output projection (1-term) -> fp32
    gemm_mma_k<<<dim3(DD / 128, NTOK / 128), 256, GSMEM>>>(
        ch, bho, out, nullptr, nullptr, INNER, INNER, /*mode=*/0);
}

// round 17
// speedup vs baseline: 1.5559x; 1.0312x over previous
#include <cuda_runtime.h>
#include <cuda_fp16.h>
#include <math.h>
#include <stdint.h>

#define BB     2
#define SS     4096
#define DD     1024
#define HH     16
#define DH     64
#define SEGLEN 512
#define PP     16
#define NWIN   8
#define INNER  1024
#define NTOK   (BB * SS)   // 8192
#define TOTKEY (SEGLEN + PP)  // 528

// ---------------- scratch (device globals; no allocation allowed) ----------
__device__ __half  g_qh[NTOK * 3 * INNER];      // qkv hi plane
__device__ __half  g_ql[NTOK * 3 * INNER];      // qkv lo plane (V cols unused)
__device__ __half  g_ah[NTOK * DD];             // rmsnorm out (fp16, single plane)
__device__ __half  g_ch[NTOK * INNER];          // attn out (fp16, single plane)
__device__ __half  g_bhq[3 * INNER * DD];       // w_qkv^T fp16  [N,K]
__device__ __half  g_bho[DD * INNER];           // w_out^T fp16  [N,K]
__device__ __half  g_pmkh[HH * PP * DH];        // pm_k hi
__device__ __half  g_pmkl[HH * PP * DH];
__device__ __half  g_pmvh[HH * PP * DH];        // pm_v (fp16 single)

// ---------------- PTX helpers (sm_80-class only; no 'a'-features) ----------
__device__ __forceinline__ uint32_t smem_u32(const void* p) {
    uint32_t a;
    asm("{ .reg .u64 t; cvta.to.shared.u64 t, %1; cvt.u32.u64 %0, t; }" : "=r"(a) : "l"(p));
    return a;
}

#define CP_ASYNC16(saddr, gptr) \
    asm volatile("cp.async.cg.shared.global [%0], [%1], 16;" :: "r"(saddr), "l"(gptr))
#define CP_COMMIT() asm volatile("cp.async.commit_group;" ::: "memory")
#define CP_WAIT(n)  asm volatile("cp.async.wait_group %0;" :: "n"(n) : "memory")

#define LDSM4(r, a)                                                                 \
    asm volatile("ldmatrix.sync.aligned.m8n8.x4.shared.b16 {%0,%1,%2,%3}, [%4];"    \
        : "=r"((r)[0]), "=r"((r)[1]), "=r"((r)[2]), "=r"((r)[3]) : "r"(a))

#define LDSM4T(r, a)                                                                \
    asm volatile("ldmatrix.sync.aligned.m8n8.x4.trans.shared.b16 {%0,%1,%2,%3}, [%4];" \
        : "=r"((r)[0]), "=r"((r)[1]), "=r"((r)[2]), "=r"((r)[3]) : "r"(a))

#define MMA_F16(d, a, b)                                                            \
    asm volatile("mma.sync.aligned.m16n8k16.row.col.f32.f16.f16.f32 "               \
        "{%0,%1,%2,%3}, {%4,%5,%6,%7}, {%8,%9}, {%0,%1,%2,%3};"                     \
        : "+f"((d)[0]), "+f"((d)[1]), "+f"((d)[2]), "+f"((d)[3])                    \
        : "r"((a)[0]), "r"((a)[1]), "r"((a)[2]), "r"((a)[3]), "r"((b)[0]), "r"((b)[1]))

__device__ __forceinline__ uint32_t packh(float x, float y) {
    __half2 t = __floats2half2_rn(x, y);
    return *reinterpret_cast<uint32_t*>(&t);
}
__device__ __forceinline__ void split2(float x, float y, uint32_t& ph, uint32_t& pl) {
    __half hx = __float2half_rn(x), hy = __float2half_rn(y);
    __half2 hp = __halves2half2(hx, hy);
    ph = *reinterpret_cast<uint32_t*>(&hp);
    pl = packh(x - __half2float(hx), y - __half2float(hy));
}

// ---------------------------------------------------------------------------
// Kernel 1: RMSNorm -> single fp16 plane.
// ---------------------------------------------------------------------------
__global__ __launch_bounds__(256) void rmsnorm_split_k(const float* __restrict__ x,
                                                       const float* __restrict__ gamma,
                                                       __half* __restrict__ Ah) {
    int row = blockIdx.x;
    int t = threadIdx.x;
    const float4* xr = reinterpret_cast<const float4*>(x + (size_t)row * DD);
    const float4* gr = reinterpret_cast<const float4*>(gamma);

    float4 v = xr[t];
    float ss = v.x * v.x + v.y * v.y + v.z * v.z + v.w * v.w;
    #pragma unroll
    for (int o = 16; o > 0; o >>= 1) ss += __shfl_xor_sync(0xffffffffu, ss, o);

    __shared__ float red[8];
    int warp = t >> 5, lane = t & 31;
    if (lane == 0) red[warp] = ss;
    __syncthreads();
    if (warp == 0) {
        float s2 = (lane < 8) ? red[lane] : 0.0f;
        #pragma unroll
        for (int o = 16; o > 0; o >>= 1) s2 += __shfl_xor_sync(0xffffffffu, s2, o);
        if (lane == 0) red[0] = s2;
    }
    __syncthreads();

    float inv = rsqrtf(red[0] * (1.0f / DD) + 1e-6f);
    float4 g = gr[t];
    uint2 hi;
    hi.x = packh(v.x * inv * g.x, v.y * inv * g.y);
    hi.y = packh(v.z * inv * g.z, v.w * inv * g.w);
    *reinterpret_cast<uint2*>(Ah + (size_t)row * DD + t * 4) = hi;
}

// ---------------------------------------------------------------------------
// Kernel 2: fused prep — weight transposes + pm-token prep in one launch.
// ---------------------------------------------------------------------------
__global__ __launch_bounds__(256) void prep_k(const float* __restrict__ Wq,
                                              const float* __restrict__ Wo,
                                              const float* __restrict__ pk,
                                              const float* __restrict__ pv,
                                              __half* __restrict__ Bq,
                                              __half* __restrict__ Bo,
                                              __half* kh, __half* kl, __half* vh) {
    if (blockIdx.z == 1 && blockIdx.x >= 32) {
        if (blockIdx.y != 0) return;
        int i = (blockIdx.x - 32) * 256 + threadIdx.x;
        if (i < HH * PP * DH) {
            float a = pk[i];
            __half h = __float2half_rn(a);
            kh[i] = h; kl[i] = __float2half_rn(a - __half2float(h));
            vh[i] = __float2half_rn(pv[i]);
        }
        return;
    }
    const float* W = (blockIdx.z == 0) ? Wq : Wo;
    __half* Bh = (blockIdx.z == 0) ? Bq : Bo;
    const int N = (blockIdx.z == 0) ? 3 * INNER : DD;
    const int K = (blockIdx.z == 0) ? DD : INNER;

    __shared__ float tile[32][33];
    int n0 = blockIdx.x * 32, k0 = blockIdx.y * 32;
    int tx = threadIdx.x & 31, ty = threadIdx.x >> 5;
    #pragma unroll
    for (int i = 0; i < 32; i += 8)
        tile[ty + i][tx] = W[(size_t)(k0 + ty + i) * N + n0 + tx];
    __syncthreads();
    #pragma unroll
    for (int i = 0; i < 32; i += 8) {
        float v = tile[tx][ty + i];
        Bh[(size_t)(n0 + ty + i) * K + k0 + tx] = __float2half_rn(v);
    }
}

// ---------------------------------------------------------------------------
// Kernel 3: HMMA fp16 GEMM, 1-term A (fp16) x fp16 B, runtime epilogue:
//   mode 1 (qkv): n0 < 2048 -> fp16 hi+lo epi; n0 >= 2048 -> fp16 hi only.
//   mode 0 (out-proj): fp32 epi.
// BK=64, 3-stage pipeline, 32KB stage (A | B), 96KB total.
// ---------------------------------------------------------------------------
#define TILEB   16384
#define NSTG    3
#define STGB    (2 * TILEB)
#define GSMEM   (NSTG * STGB)          // 96KB

__global__ __launch_bounds__(256, 1) void gemm_mma_k(const __half* __restrict__ Ah,
                                                     const __half* __restrict__ Bh,
                                                     float* __restrict__ C,
                                                     __half* __restrict__ Ch,
                                                     __half* __restrict__ Cl,
                                                     int Nld, int K, int mode) {
    extern __shared__ __align__(1024) char smem[];
    uint32_t sb = smem_u32(smem);
    const int tid = threadIdx.x;
    const int lane = tid & 31;
    const int wid = tid >> 5;
    const int m0 = blockIdx.y * 128, n0 = blockIdx.x * 128;
    const int wm = (wid & 1) * 64;
    const int wn = (wid >> 1) * 32;

    int epi;
    if (mode == 1) epi = (n0 < 2048) ? 1 : 2;
    else           epi = 0;

    float acc[4][4][4];
    #pragma unroll
    for (int i = 0; i < 4; i++)
        #pragma unroll
        for (int j = 0; j < 4; j++)
            #pragma unroll
            for (int r = 0; r < 4; r++) acc[i][j][r] = 0.0f;

    const int NC = K >> 6;             // BK = 64

    auto issue = [&](int c) {
        uint32_t base = sb + (c % NSTG) * STGB;
        #pragma unroll
        for (int tile = 0; tile < 2; ++tile) {
            const __half* gsrc = (tile == 0) ? Ah + (size_t)m0 * K + c * 64
                                             : Bh + (size_t)n0 * K + c * 64;
            #pragma unroll
            for (int it = 0; it < 4; ++it) {
                int lin = tid + it * 256;
                int r = lin >> 3, s = lin & 7;
                uint32_t dst = base + tile * TILEB + r * 128 + ((s ^ (r & 7)) << 4);
                const char* src = (const char*)(gsrc + (size_t)r * K + s * 8);
                CP_ASYNC16(dst, src);
            }
        }
        CP_COMMIT();
    };

    issue(0);
    if (NC > 1) issue(1);

    const int ra  = wm + (lane & 15);
    const int sa  = ra & 7;
    const int ha  = lane >> 4;
    const int rbl = (lane & 7) + ((lane >> 4) << 3);
    const int hb  = (lane >> 3) & 1;
    const int sbz = rbl & 7;

    for (int c = 0; c < NC; ++c) {
        if (c + 1 < NC) { CP_WAIT(1); }
        else            { CP_WAIT(0); }
        __syncthreads();
        if (c + 2 < NC) issue(c + 2);

        uint32_t base = sb + (c % NSTG) * STGB;
        uint32_t bbase = base + TILEB;
        #pragma unroll
        for (int ks = 0; ks < 4; ++ks) {
            const int kc = ks * 2;

            uint32_t aH[4][4];
            #pragma unroll
            for (int mt = 0; mt < 4; ++mt) {
                uint32_t ad = base + (ra + mt * 16) * 128 + (((kc + ha) ^ sa) << 4);
                LDSM4(aH[mt], ad);
            }
            uint32_t bH[4][2];
            #pragma unroll
            for (int np = 0; np < 2; ++np) {
                uint32_t t4[4];
                uint32_t ad = bbase + (wn + np * 16 + rbl) * 128
                            + (((kc + hb) ^ sbz) << 4);
                LDSM4(t4, ad);
                bH[np * 2][0] = t4[0]; bH[np * 2][1] = t4[1];
                bH[np * 2 + 1][0] = t4[2]; bH[np * 2 + 1][1] = t4[3];
            }
            #pragma unroll
            for (int mt = 0; mt < 4; ++mt)
                #pragma unroll
                for (int nt = 0; nt < 4; ++nt)
                    MMA_F16(acc[mt][nt], aH[mt], bH[nt]);
        }
    }

    #pragma unroll
    for (int mt = 0; mt < 4; ++mt) {
        #pragma unroll
        for (int nt = 0; nt < 4; ++nt) {
            int row = m0 + wm + mt * 16 + (lane >> 2);
            int col = n0 + wn + nt * 8 + (lane & 3) * 2;
            if (epi == 1) {
                uint32_t h0, l0, h1, l1;
                split2(acc[mt][nt][0], acc[mt][nt][1], h0, l0);
                split2(acc[mt][nt][2], acc[mt][nt][3], h1, l1);
                *reinterpret_cast<uint32_t*>(Ch + (size_t)row * Nld + col) = h0;
                *reinterpret_cast<uint32_t*>(Cl + (size_t)row * Nld + col) = l0;
                *reinterpret_cast<uint32_t*>(Ch + (size_t)(row + 8) * Nld + col) = h1;
                *reinterpret_cast<uint32_t*>(Cl + (size_t)(row + 8) * Nld + col) = l1;
            } else if (epi == 2) {
                *reinterpret_cast<uint32_t*>(Ch + (size_t)row * Nld + col) =
                    packh(acc[mt][nt][0], acc[mt][nt][1]);
                *reinterpret_cast<uint32_t*>(Ch + (size_t)(row + 8) * Nld + col) =
                    packh(acc[mt][nt][2], acc[mt][nt][3]);
            } else {
                *reinterpret_cast<float2*>(C + (size_t)row * Nld + col) =
                    make_float2(acc[mt][nt][0], acc[mt][nt][1]);
                *reinterpret_cast<float2*>(C + (size_t)(row + 8) * Nld + col) =
                    make_float2(acc[mt][nt][2], acc[mt][nt][3]);
            }
        }
    }
}

// ---------------------------------------------------------------------------
// Kernel 4: flash attention on mma.sync fp16 — R13/R16 MMA grouping.
// S: 3-term (Qh Kh + Qh Kl + Ql Kh).  PV: 1-term (fp16 P x Vh).
// ---------------------------------------------------------------------------
#define AT_QH   0
#define AT_QL   16384
#define AT_KV   32768
#define AT_KVB  24576          // 3 x 8KB
#define AT_SMEM (AT_KV + 2 * AT_KVB)   // 80KB

__global__ __launch_bounds__(256, 1) void attn_mma_k(const __half* __restrict__ qh,
                                                     const __half* __restrict__ ql,
                                                     const __half* __restrict__ pmkh,
                                                     const __half* __restrict__ pmkl,
                                                     const __half* __restrict__ pmvh,
                                                     __half* __restrict__ outh) {
    extern __shared__ __align__(1024) char smem[];
    uint32_t sb = smem_u32(smem);
    const int qt = 3 - blockIdx.x;         // heavy-first scheduling
    const int wh = blockIdx.y;
    const int b  = blockIdx.z;
    const int w  = wh >> 4;
    const int hd = wh & 15;
    const int tid = threadIdx.x;
    const int lane = tid & 31;
    const int wid = tid >> 5;
    const int tokbase = b * SS + w * SEGLEN;

    {
        #pragma unroll
        for (int t2 = 0; t2 < 2; ++t2) {
            const __half* src = t2 ? ql : qh;
            uint32_t dbase = sb + (t2 ? AT_QL : AT_QH);
            #pragma unroll
            for (int it = 0; it < 4; ++it) {
                int lin = tid + it * 256;
                int r = lin >> 3, s = lin & 7;
                CP_ASYNC16(dbase + r * 128 + ((s ^ (r & 7)) << 4),
                           src + (size_t)(tokbase + qt * 128 + r) * 3072 + hd * 64 + s * 8);
            }
        }
        CP_COMMIT();
    }

    const int nch = ((qt * 128 + 127 + PP) >> 6) + 1;

    auto stage = [&](int c, int buf) {
        int c0 = c * 64;
        uint32_t base = sb + AT_KV + buf * AT_KVB;
        #pragma unroll
        for (int tile = 0; tile < 3; ++tile) {
            const __half* pmsrc = (tile == 0) ? pmkh : (tile == 1) ? pmkl : pmvh;
            const __half* tsrc  = (tile == 1) ? ql : qh;
            const int toff = (tile < 2) ? 1024 : 2048;
            #pragma unroll
            for (int it = 0; it < 2; ++it) {
                int lin = tid + it * 256;
                int r = lin >> 3, s = lin & 7;
                int j = c0 + r;
                uint32_t dst = base + tile * 8192 + r * 128 + ((s ^ (r & 7)) << 4);
                if (j < PP) {
                    CP_ASYNC16(dst, pmsrc + (hd * PP + j) * 64 + s * 8);
                } else if (j < TOTKEY) {
                    CP_ASYNC16(dst, tsrc + (size_t)(tokbase + j - PP) * 3072 + toff + hd * 64 + s * 8);
                } else {
                    uint4 z = make_uint4(0, 0, 0, 0);
                    *reinterpret_cast<uint4*>(smem + (dst - sb)) = z;
                }
            }
        }
        CP_COMMIT();
    };

    stage(0, 0);
    CP_WAIT(0);
    __syncthreads();

    uint32_t qfh[4][4], qfl[4][4];
    const int ra = wid * 16 + (lane & 15);
    const int ha = lane >> 4;
    #pragma unroll
    for (int ks = 0; ks < 4; ++ks) {
        uint32_t ad = sb + AT_QH + ra * 128 + (((ks * 2 + ha) ^ (ra & 7)) << 4);
        LDSM4(qfh[ks], ad);
        LDSM4(qfl[ks], ad + AT_QL);
    }

    const int lr = lane >> 2;
    const int i0 = qt * 128 + wid * 16 + lr;
    const int i1 = i0 + 8;
    float m0 = -1e30f, m1 = -1e30f, l0 = 0.0f, l1 = 0.0f;
    float oacc[8][4];
    #pragma unroll
    for (int d = 0; d < 8; ++d)
        #pragma unroll
        for (int r = 0; r < 4; ++r) oacc[d][r] = 0.0f;

    const int rbl = (lane & 7) + ((lane >> 4) << 3);
    const int hb  = (lane >> 3) & 1;
    const int sbz = rbl & 7;
    const int vrow = lane & 15;
    const int vhi  = lane >> 4;

    for (int c = 0; c < nch; ++c) {
        if (c + 1 < nch) { stage(c + 1, (c + 1) & 1); CP_WAIT(1); }
        else            { CP_WAIT(0); }
        __syncthreads();

        uint32_t kb = sb + AT_KV + (c & 1) * AT_KVB;
        uint32_t vb = kb + 2 * 8192;
        int c0 = c * 64;

        float sacc[8][4];
        #pragma unroll
        for (int n = 0; n < 8; ++n)
            #pragma unroll
            for (int r = 0; r < 4; ++r) sacc[n][r] = 0.0f;

        #pragma unroll
        for (int ks = 0; ks < 4; ++ks) {
            #pragma unroll
            for (int np = 0; np < 4; ++np) {
                uint32_t kh4[4], kl4[4];
                uint32_t ad = kb + (np * 16 + rbl) * 128 + (((ks * 2 + hb) ^ sbz) << 4);
                LDSM4(kh4, ad);
                LDSM4(kl4, ad + 8192);
                MMA_F16(sacc[2 * np],     qfh[ks], (&kh4[0]));
                MMA_F16(sacc[2 * np],     qfh[ks], (&kl4[0]));
                MMA_F16(sacc[2 * np],     qfl[ks], (&kh4[0]));
                MMA_F16(sacc[2 * np + 1], qfh[ks], (&kh4[2]));
                MMA_F16(sacc[2 * np + 1], qfh[ks], (&kl4[2]));
                MMA_F16(sacc[2 * np + 1], qfl[ks], (&kh4[2]));
            }
        }

        const float sc = 0.125f;
        float rm0 = -1e30f, rm1 = -1e30f;
        #pragma unroll
        for (int n = 0; n < 8; ++n) {
            int jb = c0 + n * 8 + (lane & 3) * 2;
            #pragma unroll
            for (int r = 0; r < 4; ++r) {
                int j = jb + (r & 1);
                int i = (r < 2) ? i0 : i1;
                bool valid = (j < PP) | (i + PP >= j);
                float z = valid ? sacc[n][r] * sc : -1e30f;
                sacc[n][r] = z;
                if (r < 2) rm0 = fmaxf(rm0, z); else rm1 = fmaxf(rm1, z);
            }
        }
        rm0 = fmaxf(rm0, __shfl_xor_sync(0xffffffffu, rm0, 1));
        rm0 = fmaxf(rm0, __shfl_xor_sync(0xffffffffu, rm0, 2));
        rm1 = fmaxf(rm1, __shfl_xor_sync(0xffffffffu, rm1, 1));
        rm1 = fmaxf(rm1, __shfl_xor_sync(0xffffffffu, rm1, 2));

        float mn0 = fmaxf(m0, rm0), mn1 = fmaxf(m1, rm1);
        float corr0 = __expf(m0 - mn0), corr1 = __expf(m1 - mn1);
        m0 = mn0; m1 = mn1;

        float rs0 = 0.0f, rs1 = 0.0f;
        #pragma unroll
        for (int n = 0; n < 8; ++n) {
            float p0 = __expf(sacc[n][0] - m0);
            float p1 = __expf(sacc[n][1] - m0);
            float p2 = __expf(sacc[n][2] - m1);
            float p3 = __expf(sacc[n][3] - m1);
            sacc[n][0] = p0; sacc[n][1] = p1; sacc[n][2] = p2; sacc[n][3] = p3;
            rs0 += p0 + p1; rs1 += p2 + p3;
        }
        rs0 += __shfl_xor_sync(0xffffffffu, rs0, 1);
        rs0 += __shfl_xor_sync(0xffffffffu, rs0, 2);
        rs1 += __shfl_xor_sync(0xffffffffu, rs1, 1);
        rs1 += __shfl_xor_sync(0xffffffffu, rs1, 2);
        l0 = l0 * corr0 + rs0;
        l1 = l1 * corr1 + rs1;

        #pragma unroll
        for (int d = 0; d < 8; ++d) {
            oacc[d][0] *= corr0; oacc[d][1] *= corr0;
            oacc[d][2] *= corr1; oacc[d][3] *= corr1;
        }

        // ---- PV: 1-term fp16 P (rounded) x Vh ----
        #pragma unroll
        for (int ks = 0; ks < 4; ++ks) {
            uint32_t pah[4];
            pah[0] = packh(sacc[2 * ks][0],     sacc[2 * ks][1]);
            pah[1] = packh(sacc[2 * ks][2],     sacc[2 * ks][3]);
            pah[2] = packh(sacc[2 * ks + 1][0], sacc[2 * ks + 1][1]);
            pah[3] = packh(sacc[2 * ks + 1][2], sacc[2 * ks + 1][3]);

            #pragma unroll
            for (int dt2 = 0; dt2 < 4; ++dt2) {
                int krow = ks * 16 + vrow;
                uint32_t ad = vb + krow * 128 + (((dt2 * 2 + vhi) ^ (krow & 7)) << 4);
                uint32_t vh4[4];
                LDSM4T(vh4, ad);
                MMA_F16(oacc[2 * dt2],     pah, (&vh4[0]));
                MMA_F16(oacc[2 * dt2 + 1], pah, (&vh4[2]));
            }
        }
        __syncthreads();
    }

    float il0 = 1.0f / l0, il1 = 1.0f / l1;
    size_t tok0 = (size_t)tokbase + i0;
    size_t tok1 = (size_t)tokbase + i1;
    #pragma unroll
    for (int d = 0; d < 8; ++d) {
        int col = hd * 64 + d * 8 + (lane & 3) * 2;
        *reinterpret_cast<uint32_t*>(outh + tok0 * 1024 + col) =
            packh(oacc[d][0] * il0, oacc[d][1] * il0);
        *reinterpret_cast<uint32_t*>(outh + tok1 * 1024 + col) =
            packh(oacc[d][2] * il1, oacc[d][3] * il1);
    }
}

// ---------------------------------------------------------------------------
extern "C" void kernel_launch(void* const* d_in, const int* in_sizes, int n_in,
                              void* d_out, int out_size) {
    const float* x     = (const float*)d_in[0];
    const float* gamma = (const float*)d_in[1];
    const float* w_qkv = (const float*)d_in[2];
    const float* w_out = (const float*)d_in[3];
    const float* pm_k  = (const float*)d_in[4];
    const float* pm_v  = (const float*)d_in[5];
    float* out = (float*)d_out;

    __half *qh, *ql, *ah, *ch, *bhq, *bho;
    __half *pmkh, *pmkl, *pmvh;
    cudaGetSymbolAddress((void**)&qh,  g_qh);
    cudaGetSymbolAddress((void**)&ql,  g_ql);
    cudaGetSymbolAddress((void**)&ah,  g_ah);
    cudaGetSymbolAddress((void**)&ch,  g_ch);
    cudaGetSymbolAddress((void**)&bhq, g_bhq);
    cudaGetSymbolAddress((void**)&bho, g_bho);
    cudaGetSymbolAddress((void**)&pmkh, g_pmkh);
    cudaGetSymbolAddress((void**)&pmkl, g_pmkl);
    cudaGetSymbolAddress((void**)&pmvh, g_pmvh);

    cudaFuncSetAttribute(gemm_mma_k, cudaFuncAttributeMaxDynamicSharedMemorySize, GSMEM);
    cudaFuncSetAttribute(attn_mma_k, cudaFuncAttributeMaxDynamicSharedMemorySize, AT_SMEM);

    // 1) RMSNorm -> fp16
    rmsnorm_split_k<<<NTOK, 256>>>(x, gamma, ah);

    // 2) fused prep: both weight transposes + pm tokens in one launch
    prep_k<<<dim3(96, 32, 2), 256>>>(w_qkv, w_out, pm_k, pm_v,
                                     bhq, bho, pmkh, pmkl, pmvh);

    // 3) QKV projection (1-term A): x<16 -> QK (hi+lo epi); x>=16 -> V (hi epi)
    gemm_mma_k<<<dim3(24, NTOK / 128), 256, GSMEM>>>(
        ah, bhq, nullptr, qh, ql, 3 * INNER, DD, /*mode=*/1);

    // 4) attention on tensor cores (3-term S, 1-term PV), heavy-first
    attn_mma_k<<<dim3(SEGLEN / 128, NWIN * HH, BB), 256, AT_SMEM>>>(
        qh, ql, pmkh, pmkl, pmvh, ch);

    // 5) output projection (1-term) -> fp32
    gemm_mma_k<<<dim3(DD / 128, NTOK / 128), 256, GSMEM>>>(
        ch, bho, out, nullptr, nullptr, INNER, INNER, /*mode=*/0);
}